// round 1
// baseline (speedup 1.0000x reference)
#include <cuda_runtime.h>
#include <cuda_bf16.h>
#include <stdint.h>

// ---------------------------------------------------------------------------
// SPMoEAdaptor fused kernel (2 soft-MoE layers + residual) for sm_103a.
//
// Math per layer:  gates = softmax(x @ Wg)                       [N,4]
//                  Y     = x @ [W_0 | W_1 | W_2 | W_3]           [N,256]
//                  h[n]  = sum_e g[n,e] * (Y[n, e*64: ] - c_e)   c_e = b_e @ W_e
// Both layers fused per 128-token tile, all intermediates in registers.
// bf16 MMA (m16n8k16, fp32 accum); residual added in exact fp32.
// ---------------------------------------------------------------------------

#define DD 64
#define EE 4
#define NW 264          // 256 expert cols + 4 gate cols + 4 zero pad
#define WS_STRIDE 20    // uint2 per weight row in smem (16 payload + 4 pad = 160B)

// Prepacked weights: [layer][n][kk][j] ; each uint2 = {bf16x2(k=kk*16+2j,+1), bf16x2(k=kk*16+2j+8,+9)}
__device__ uint2 g_wpack[2][NW][4][4];
__device__ float g_c[2][EE][DD];   // bias correction c_e[f] = sum_d b[e,d]*W[e,d,f]

__device__ __forceinline__ uint32_t pack_bf16x2(float lo, float hi) {
    uint32_t r;
    asm("cvt.rn.bf16x2.f32 %0, %1, %2;" : "=r"(r) : "f"(hi), "f"(lo));
    return r;
}

// ------------------------------ prep kernel --------------------------------
__global__ void prep_kernel(const float* __restrict__ wg_a, const float* __restrict__ we_a,
                            const float* __restrict__ be_a,
                            const float* __restrict__ wg_b, const float* __restrict__ we_b,
                            const float* __restrict__ be_b) {
    const int L = blockIdx.x;
    const float* wg = L ? wg_b : wg_a;
    const float* we = L ? we_b : we_a;
    const float* be = L ? be_b : be_a;

    for (int idx = threadIdx.x; idx < NW * 16; idx += blockDim.x) {
        int n  = idx >> 4;
        int kk = (idx >> 2) & 3;
        int j  = idx & 3;
        float v[4];
#pragma unroll
        for (int h = 0; h < 4; h++) {
            int d = kk * 16 + 2 * j + (h >> 1) * 8 + (h & 1);
            float w;
            if (n < 256)        w = we[((n >> 6) * DD + d) * DD + (n & 63)]; // W_e[d][f], e=n>>6, f=n&63
            else if (n < 260)   w = wg[d * EE + (n - 256)];                  // w_gate[d][e]
            else                w = 0.0f;
            v[h] = w;
        }
        uint2 u;
        u.x = pack_bf16x2(v[0], v[1]);
        u.y = pack_bf16x2(v[2], v[3]);
        g_wpack[L][n][kk][j] = u;
    }
    for (int idx = threadIdx.x; idx < EE * DD; idx += blockDim.x) {
        int e = idx >> 6, f = idx & 63;
        float s = 0.0f;
        for (int d = 0; d < DD; d++) s += be[e * DD + d] * we[(e * DD + d) * DD + f];
        g_c[L][e][f] = s;
    }
}

// ------------------------------ MMA helpers --------------------------------
__device__ __forceinline__ void mma16816(float c[4], const uint32_t a[4], uint32_t b0, uint32_t b1) {
    asm volatile(
        "mma.sync.aligned.m16n8k16.row.col.f32.bf16.bf16.f32 "
        "{%0,%1,%2,%3}, {%4,%5,%6,%7}, {%8,%9}, {%0,%1,%2,%3};"
        : "+f"(c[0]), "+f"(c[1]), "+f"(c[2]), "+f"(c[3])
        : "r"(a[0]), "r"(a[1]), "r"(a[2]), "r"(a[3]), "r"(b0), "r"(b1));
}

// One [16 x 8] n-tile over full K=64 (4 k-steps)
__device__ __forceinline__ void ntile(float acc[4], const uint32_t A[4][4],
                                      const uint2* __restrict__ ws, int nbase, int lane) {
    acc[0] = acc[1] = acc[2] = acc[3] = 0.0f;
    const uint2* wrow = ws + (nbase + (lane >> 2)) * WS_STRIDE + (lane & 3);
#pragma unroll
    for (int kk = 0; kk < 4; kk++) {
        uint2 b = wrow[kk * 4];
        mma16816(acc, A[kk], b.x, b.y);
    }
}

__device__ __forceinline__ void softmax4(float g[4], float a, float b, float c, float d) {
    float m = fmaxf(fmaxf(a, b), fmaxf(c, d));
    float e0 = __expf(a - m), e1 = __expf(b - m), e2 = __expf(c - m), e3 = __expf(d - m);
    float inv = 1.0f / (e0 + e1 + e2 + e3);
    g[0] = e0 * inv; g[1] = e1 * inv; g[2] = e2 * inv; g[3] = e3 * inv;
}

// Gate probs for rows (qr) and (qr+8) of the warp tile
__device__ __forceinline__ void gates(float glo[4], float ghi[4], const uint32_t A[4][4],
                                      const uint2* __restrict__ ws, int lane) {
    float acc[4];
    ntile(acc, A, ws, 256, lane);   // gate panel: Wall rows 256..263
    const unsigned full = 0xffffffffu;
    int qb = lane & ~3;
    // logits col e: lane qc=0 holds cols {0,1}, qc=1 holds cols {2,3}
    float l0 = __shfl_sync(full, acc[0], qb);
    float l1 = __shfl_sync(full, acc[1], qb);
    float l2 = __shfl_sync(full, acc[0], qb + 1);
    float l3 = __shfl_sync(full, acc[1], qb + 1);
    float h0 = __shfl_sync(full, acc[2], qb);
    float h1 = __shfl_sync(full, acc[3], qb);
    float h2 = __shfl_sync(full, acc[2], qb + 1);
    float h3 = __shfl_sync(full, acc[3], qb + 1);
    softmax4(glo, l0, l1, l2, l3);
    softmax4(ghi, h0, h1, h2, h3);
}

// One full MoE layer: A fragments in, h[8][4] fp32 fragments out
__device__ __forceinline__ void moe_layer(float h[8][4], const uint32_t A[4][4],
                                          const uint2* __restrict__ ws,
                                          const float* __restrict__ cl, int lane) {
    float glo[4], ghi[4];
    gates(glo, ghi, A, ws, lane);
#pragma unroll
    for (int s = 0; s < 8; s++) {
        h[s][0] = 0.0f; h[s][1] = 0.0f; h[s][2] = 0.0f; h[s][3] = 0.0f;
    }
    int qc = lane & 3;
#pragma unroll
    for (int e = 0; e < 4; e++) {
#pragma unroll
        for (int s = 0; s < 8; s++) {
            float acc[4];
            ntile(acc, A, ws, (e * 8 + s) * 8, lane);
            int f = s * 8 + qc * 2;
            float c0 = cl[e * 64 + f];
            float c1 = cl[e * 64 + f + 1];
            h[s][0] += glo[e] * (acc[0] - c0);
            h[s][1] += glo[e] * (acc[1] - c1);
            h[s][2] += ghi[e] * (acc[2] - c0);
            h[s][3] += ghi[e] * (acc[3] - c1);
        }
    }
}

// ------------------------------ main kernel --------------------------------
__global__ __launch_bounds__(256, 2)
void moe_main_kernel(const float* __restrict__ x, float* __restrict__ out, int Ntok) {
    extern __shared__ uint2 smem[];
    uint2* ws0 = smem;
    uint2* ws1 = smem + NW * WS_STRIDE;
    float* cs  = (float*)(smem + 2 * NW * WS_STRIDE);   // [2][256]

    // Stage weights into smem (padded rows: conflict-free B-fragment LDS.64)
    for (int idx = threadIdx.x; idx < NW * 16; idx += 256) {
        int n = idx >> 4, r = idx & 15;
        ws0[n * WS_STRIDE + r] = ((const uint2*)g_wpack[0])[idx];
        ws1[n * WS_STRIDE + r] = ((const uint2*)g_wpack[1])[idx];
    }
    for (int idx = threadIdx.x; idx < 512; idx += 256)
        cs[idx] = ((const float*)g_c)[idx];
    __syncthreads();

    const int warp = threadIdx.x >> 5;
    const int lane = threadIdx.x & 31;
    const int qr = lane >> 2;
    const int qc = lane & 3;
    const int tok0 = blockIdx.x * 128 + warp * 16 + qr;   // rows tok0 and tok0+8

    const int ta = min(tok0, Ntok - 1);
    const int tb = min(tok0 + 8, Ntok - 1);
    const float* xa = x + (size_t)ta * DD;
    const float* xb = x + (size_t)tb * DD;

    // ---- layer 1 A fragments straight from gmem (fp32 -> bf16) ----
    uint32_t A1[4][4];
#pragma unroll
    for (int kk = 0; kk < 4; kk++) {
        int c = kk * 16 + qc * 2;
        float2 v0 = *(const float2*)(xa + c);
        float2 v1 = *(const float2*)(xb + c);
        float2 v2 = *(const float2*)(xa + c + 8);
        float2 v3 = *(const float2*)(xb + c + 8);
        A1[kk][0] = pack_bf16x2(v0.x, v0.y);
        A1[kk][1] = pack_bf16x2(v1.x, v1.y);
        A1[kk][2] = pack_bf16x2(v2.x, v2.y);
        A1[kk][3] = pack_bf16x2(v3.x, v3.y);
    }

    // ---- layer 1 ----
    float h[8][4];
    moe_layer(h, A1, ws0, cs, lane);

    // ---- h accumulator fragments ARE layer-2 A fragments (same lane map) ----
    uint32_t A2[4][4];
#pragma unroll
    for (int kk = 0; kk < 4; kk++) {
        A2[kk][0] = pack_bf16x2(h[2 * kk][0],     h[2 * kk][1]);
        A2[kk][1] = pack_bf16x2(h[2 * kk][2],     h[2 * kk][3]);
        A2[kk][2] = pack_bf16x2(h[2 * kk + 1][0], h[2 * kk + 1][1]);
        A2[kk][3] = pack_bf16x2(h[2 * kk + 1][2], h[2 * kk + 1][3]);
    }

    // ---- layer 2 ----
    float h2[8][4];
    moe_layer(h2, A2, ws1, cs + 256, lane);

    // ---- residual (exact fp32 reload, L2-hot) + store ----
    const bool va = (tok0 < Ntok);
    const bool vb = (tok0 + 8 < Ntok);
#pragma unroll
    for (int s = 0; s < 8; s++) {
        int f = s * 8 + qc * 2;
        if (va) {
            float2 xr = *(const float2*)(x + (size_t)tok0 * DD + f);
            float2 o;
            o.x = h2[s][0] + xr.x;
            o.y = h2[s][1] + xr.y;
            *(float2*)(out + (size_t)tok0 * DD + f) = o;
        }
        if (vb) {
            float2 xr = *(const float2*)(x + (size_t)(tok0 + 8) * DD + f);
            float2 o;
            o.x = h2[s][2] + xr.x;
            o.y = h2[s][3] + xr.y;
            *(float2*)(out + (size_t)(tok0 + 8) * DD + f) = o;
        }
    }
}

// ------------------------------ launch -------------------------------------
extern "C" void kernel_launch(void* const* d_in, const int* in_sizes, int n_in,
                              void* d_out, int out_size) {
    const float* x    = (const float*)d_in[0];
    const float* wg_a = (const float*)d_in[1];
    const float* we_a = (const float*)d_in[2];
    const float* be_a = (const float*)d_in[3];
    const float* wg_b = (const float*)d_in[4];
    const float* we_b = (const float*)d_in[5];
    const float* be_b = (const float*)d_in[6];
    const int Ntok = in_sizes[0] / DD;

    prep_kernel<<<2, 256>>>(wg_a, we_a, be_a, wg_b, we_b, be_b);

    const int smem_bytes = 2 * NW * WS_STRIDE * (int)sizeof(uint2) + 512 * (int)sizeof(float);
    cudaFuncSetAttribute(moe_main_kernel, cudaFuncAttributeMaxDynamicSharedMemorySize, smem_bytes);

    const int grid = (Ntok + 127) / 128;
    moe_main_kernel<<<grid, 256, smem_bytes>>>(x, (float*)d_out, Ntok);
}